// round 9
// baseline (speedup 1.0000x reference)
#include <cuda_runtime.h>
#include <cuda_fp16.h>
#include <cstdint>

// ============================================================================
// Portable PTX helpers (mma.sync / ldmatrix / cp.async only — no 'a'-gated ops)
// ============================================================================

__device__ __forceinline__ uint32_t smem_to_u32(const void* smem_ptr) {
    uint32_t addr;
    asm("{ .reg .u64 tmp; cvta.to.shared.u64 tmp, %1; cvt.u32.u64 %0, tmp; }"
        : "=r"(addr) : "l"(smem_ptr));
    return addr;
}

__device__ __forceinline__ void cp_async16(uint32_t dst, const void* src) {
    asm volatile("cp.async.cg.shared.global [%0], [%1], 16;"
                 :: "r"(dst), "l"(__cvta_generic_to_global(src)));
}
__device__ __forceinline__ void cp_commit() {
    asm volatile("cp.async.commit_group;" ::: "memory");
}
__device__ __forceinline__ void cp_wait0() {
    asm volatile("cp.async.wait_group 0;" ::: "memory");
}

__device__ __forceinline__ void ldmx4(uint32_t* r, uint32_t addr) {
    asm volatile("ldmatrix.sync.aligned.m8n8.x4.shared.b16 {%0,%1,%2,%3}, [%4];"
                 : "=r"(r[0]), "=r"(r[1]), "=r"(r[2]), "=r"(r[3]) : "r"(addr));
}

__device__ __forceinline__ void mma16816(float* c, const uint32_t* a, const uint32_t* b) {
    asm volatile(
        "mma.sync.aligned.m16n8k16.row.col.f32.f16.f16.f32 "
        "{%0,%1,%2,%3}, {%4,%5,%6,%7}, {%8,%9}, {%0,%1,%2,%3};"
        : "+f"(c[0]), "+f"(c[1]), "+f"(c[2]), "+f"(c[3])
        : "r"(a[0]), "r"(a[1]), "r"(a[2]), "r"(a[3]), "r"(b[0]), "r"(b[1]));
}

// ============================================================================
// Problem constants
// ============================================================================
static constexpr int DIN = 256;    // K
static constexpr int BM  = 128;    // CTA M tile
static constexpr int BN  = 256;    // CTA N tile
static constexpr int BK  = 64;     // K chunk (4 k16 steps)
static constexpr int NCHUNK = DIN / BK;  // 4 (even -> tile-boundary stage reuse safe)

static constexpr int A_STRIDE = 144;   // 64 fp16 (128B) + 16B pad -> conflict-free
static constexpr int B_STRIDE = 528;   // 256 fp16 (512B) + 16B pad -> conflict-free
static constexpr int A_STAGE  = BM * A_STRIDE;   // 18432

// smem layout (dynamic, bytes)
static constexpr int SM_B    = 0;                   // 256 * 528 = 135168 (persistent per nt)
static constexpr int SM_A    = 135168;              // 2 stages * 18432 = 36864
static constexpr int SM_BIAS = 172032;              // 256 floats = 1024
static constexpr int SMEM_SZ = 173056;

// ============================================================================
// Device scratch (no allocation allowed -> __device__ globals)
// ============================================================================
__device__ float  g_bias[512];           // [0:256) combined bias c1, [256:512) out bias c2
__device__ float  g_W1[256 * 256];
__device__ __half g_Bh[512 * 256];       // fused weight, [n][k] row-major, fp16

// ============================================================================
// Prep kernels (measured-good): grid 512 (row x col-half), block 128,
// 8 acc chains, unroll 16.
// ============================================================================

__device__ __forceinline__ float warp_sum(float v) {
#pragma unroll
    for (int o = 16; o > 0; o >>= 1) v += __shfl_xor_sync(0xffffffffu, v, o);
    return v;
}

// Block (o, h): W1[o, h*128 + tid] = sum_i (gate*Wc[o,i]) * Wp[i, col].
// h==0 block also computes c1[o] and (o%32==0) the gate outputs.
__global__ void __launch_bounds__(128, 8)
prep_w1(const float* __restrict__ Wc, const float* __restrict__ Wp,
        const float* __restrict__ bp,
        const float* __restrict__ pre, const float* __restrict__ post,
        float* __restrict__ out_tail) {
    __shared__ float sWc[256];
    __shared__ float sRed[4];
    __shared__ float sGate;
    const int o   = blockIdx.x >> 1;
    const int h   = blockIdx.x & 1;
    const int tid = threadIdx.x;
    const int col = h * 128 + tid;
    const int ko  = o >> 5;

    if (tid < 32) {
        float a = pre[ko * 256 + tid];
        float b = post[ko * 32 + tid];
        float sp = warp_sum(a * a);
        float sq = warp_sum(b * b);
        float np = fmaxf(sqrtf(sp), 1e-12f);
        float nq = fmaxf(sqrtf(sq), 1e-12f);
        float d  = warp_sum((a / np) * (b / nq));
        if (tid == 0) {
            float align = 1.0f / (1.0f + expf(-d));
            float g = (align >= 0.3f) ? align : 0.0f;
            sGate = g;
            if ((o & 31) == 0 && h == 0) {
                out_tail[ko] = g;          // alignments
                out_tail[8 + ko] = 1.0f;   // allocation_mask
            }
        }
    }
    __syncthreads();
    const float g = sGate;
    {
        float w0 = Wc[o * 256 + tid] * g;
        float w1 = Wc[o * 256 + 128 + tid] * g;
        sWc[tid] = w0;
        sWc[128 + tid] = w1;
    }
    __syncthreads();

    float acc[8] = {0.f, 0.f, 0.f, 0.f, 0.f, 0.f, 0.f, 0.f};
#pragma unroll 16
    for (int i = 0; i < 256; ++i)
        acc[i & 7] += sWc[i] * Wp[i * 256 + col];
    float r = ((acc[0] + acc[1]) + (acc[2] + acc[3])) +
              ((acc[4] + acc[5]) + (acc[6] + acc[7]));
    g_W1[o * 256 + col] = r;
    g_Bh[o * 256 + col] = __float2half_rn(r);

    if (h == 0) {
        float p = sWc[tid] * bp[tid] + sWc[128 + tid] * bp[128 + tid];
        p = warp_sum(p);
        if ((tid & 31) == 0) sRed[tid >> 5] = p;
        __syncthreads();
        if (tid == 0)
            g_bias[o] = (sRed[0] + sRed[1]) + (sRed[2] + sRed[3]);
    }
}

// Block (o, h): W2[o, col] = sum_i Wo[o,i] * W1[i, col]; h==0 computes c2[o].
__global__ void __launch_bounds__(128, 8)
prep_w2(const float* __restrict__ Wo, const float* __restrict__ bo) {
    __shared__ float sWo[256];
    __shared__ float sRed[4];
    const int o   = blockIdx.x >> 1;
    const int h   = blockIdx.x & 1;
    const int tid = threadIdx.x;
    const int col = h * 128 + tid;

    sWo[tid]       = Wo[o * 256 + tid];
    sWo[128 + tid] = Wo[o * 256 + 128 + tid];
    __syncthreads();

    float acc[8] = {0.f, 0.f, 0.f, 0.f, 0.f, 0.f, 0.f, 0.f};
#pragma unroll 16
    for (int i = 0; i < 256; ++i)
        acc[i & 7] += sWo[i] * g_W1[i * 256 + col];
    float r = ((acc[0] + acc[1]) + (acc[2] + acc[3])) +
              ((acc[4] + acc[5]) + (acc[6] + acc[7]));
    g_Bh[(256 + o) * 256 + col] = __float2half_rn(r);

    if (h == 0) {
        float p = sWo[tid] * g_bias[tid] + sWo[128 + tid] * g_bias[128 + tid];
        p = warp_sum(p);
        if ((tid & 31) == 0) sRed[tid >> 5] = p;
        __syncthreads();
        if (tid == 0)
            g_bias[256 + o] = (sRed[0] + sRed[1]) + (sRed[2] + sRed[3]) + bo[o];
    }
}

// ============================================================================
// Main fused GEMM (persistent CTAs): C[131072 x 512] = x @ B^T, fp16 HMMA,
// fp32 accumulate. CTA tile 128x256, 16 warps (4M x 4N), 1 CTA/SM.
// Units ordered nt-major: u in [0,1024) -> combined half, [1024,2048) -> out
// half; B (+bias) reloaded only when nt changes (<= 2x per CTA).
// Per tile: A LDG->regs (static pre[4]) -> fp16 -> STS, 2-stage ring of K=64
// chunks, prefetch distance 1, one __syncthreads per chunk.
// ============================================================================
__global__ void __launch_bounds__(512, 1)
fused_main(const float* __restrict__ x, float* __restrict__ out,
           int Brows, int nunits) {
    extern __shared__ char smem[];
    const uint32_t sb = smem_to_u32(smem);
    const int tid  = threadIdx.x;
    const int wid  = tid >> 5, lane = tid & 31;
    const int wm   = wid & 3;               // 4 M-warps of 32 rows
    const int wn   = wid >> 2;              // 4 N-warps of 64 cols
    const int half = nunits >> 1;

    // per-thread x mapping: 4 threads/row, 4 consecutive 16B segs each
    const int prow  = tid >> 2;                  // row 0..127
    const int pseg0 = (tid & 3) * 4;             // segs {0..3},{4..7},{8..11},{12..15}

    const int arow  = wm * 32 + (lane & 15);
    const uint32_t acolb = ((lane >> 4) & 1) * 16;
    const int brow0 = wn * 64 + ((lane & 7) | ((lane >> 4) << 3));
    const uint32_t bcolb = ((lane >> 3) & 1) * 16;

    int curnt = -1;

    for (int u = blockIdx.x; u < nunits; u += gridDim.x) {
        const int nt = (u >= half) ? 1 : 0;
        const int mt = (u >= half) ? (u - half) : u;

        // ---- (re)load persistent B tile + bias when the N-half changes ----
        if (nt != curnt) {
            __syncthreads();   // all warps done with prior tile's MMA/epilogue
            const __half* Bg = g_Bh + (size_t)nt * BN * DIN;
            const uint32_t bd = sb + SM_B;
#pragma unroll
            for (int i = 0; i < 16; ++i) {
                int idx = tid + 512 * i;            // 8192 x 16B
                int row = idx >> 5, kseg = idx & 31;
                cp_async16(bd + row * B_STRIDE + kseg * 16, Bg + row * DIN + kseg * 8);
            }
            if (tid < 64)
                cp_async16(sb + SM_BIAS + tid * 16, g_bias + nt * BN + tid * 4);
            cp_commit();
            curnt = nt;
        }

        const float* xrow = x + (size_t)mt * BM * DIN + prow * DIN + pseg0 * 4;

        float acc[2][8][4];
#pragma unroll
        for (int m = 0; m < 2; m++)
#pragma unroll
            for (int n = 0; n < 8; n++)
#pragma unroll
                for (int k = 0; k < 4; k++) acc[m][n][k] = 0.f;

        float4 pre[4];
#pragma unroll
        for (int j = 0; j < 4; ++j)
            pre[j] = *(const float4*)(xrow + j * 4);

#pragma unroll 1
        for (int c = 0; c < NCHUNK; ++c) {
            const int s = c & 1;

            // ---- convert prefetched fp32 -> fp16, STS to A stage s ----
            {
                char* As = smem + SM_A + s * A_STAGE;
#pragma unroll
                for (int j = 0; j < 4; ++j) {
                    __half h0 = __float2half_rn(pre[j].x), h1 = __float2half_rn(pre[j].y);
                    __half h2 = __float2half_rn(pre[j].z), h3 = __float2half_rn(pre[j].w);
                    uint2 hp;
                    hp.x = (uint32_t)__half_as_ushort(h0) | ((uint32_t)__half_as_ushort(h1) << 16);
                    hp.y = (uint32_t)__half_as_ushort(h2) | ((uint32_t)__half_as_ushort(h3) << 16);
                    *(uint2*)(As + prow * A_STRIDE + (pseg0 + j) * 8) = hp;
                }
            }
            if (c == 0) cp_wait0();   // B/bias resident (no-op when queue empty)
            __syncthreads();

            // ---- prefetch next chunk (LDG in flight under 64 MMAs) ----
            if (c + 1 < NCHUNK) {
#pragma unroll
                for (int j = 0; j < 4; ++j)
                    pre[j] = *(const float4*)(xrow + (c + 1) * BK + j * 4);
            }

            // ---- 4 k16 steps of MMA ----
            const uint32_t abase = sb + SM_A + s * A_STAGE;
            const uint32_t bks   = sb + SM_B + (uint32_t)(c * 128);
#pragma unroll
            for (int ks = 0; ks < 4; ++ks) {
                uint32_t af[2][4], bf[4][4];
#pragma unroll
                for (int m = 0; m < 2; ++m)
                    ldmx4(af[m], abase + (uint32_t)((arow + m * 16) * A_STRIDE) + acolb + ks * 32);
#pragma unroll
                for (int p = 0; p < 4; ++p)
                    ldmx4(bf[p], bks + (uint32_t)((brow0 + p * 16) * B_STRIDE) + bcolb + ks * 32);
#pragma unroll
                for (int m = 0; m < 2; ++m)
#pragma unroll
                    for (int n = 0; n < 8; ++n)
                        mma16816(acc[m][n], af[m], &bf[n >> 1][(n & 1) * 2]);
            }
        }

        // ---- epilogue: add fused bias (smem), write this unit's output half ----
        const float* bias_s = (const float*)(smem + SM_BIAS);
        // nt==0 -> combined block (second Brows*256 of out); nt==1 -> out block (first)
        float* hbase = out + (nt ? (size_t)0 : (size_t)Brows * 256);
#pragma unroll
        for (int m = 0; m < 2; ++m) {
            const int row = mt * BM + wm * 32 + m * 16 + (lane >> 2);
            float* rp = hbase + (size_t)row * 256;
#pragma unroll
            for (int n = 0; n < 8; ++n) {
                const int ln = wn * 64 + n * 8 + (lane & 3) * 2;   // 0..255 column
                const float b0 = bias_s[ln], b1 = bias_s[ln + 1];
                *(float2*)(rp + ln)           = make_float2(acc[m][n][0] + b0, acc[m][n][1] + b1);
                *(float2*)(rp + ln + 8 * 256) = make_float2(acc[m][n][2] + b0, acc[m][n][3] + b1);
            }
        }
    }
}

// ============================================================================
// kernel_launch
// ============================================================================
extern "C" void kernel_launch(void* const* d_in, const int* in_sizes, int n_in,
                              void* d_out, int out_size) {
    const float* x    = (const float*)d_in[0];
    const float* Wp   = (const float*)d_in[1];
    const float* bp   = (const float*)d_in[2];
    const float* pre  = (const float*)d_in[3];
    const float* post = (const float*)d_in[4];
    const float* Wc   = (const float*)d_in[5];
    const float* Wo   = (const float*)d_in[6];
    const float* bo   = (const float*)d_in[7];
    float* out = (float*)d_out;
    const int Brows  = in_sizes[0] / 256;     // 131072
    const int nunits = (Brows / BM) * 2;      // 2048

    cudaFuncSetAttribute(fused_main, cudaFuncAttributeMaxDynamicSharedMemorySize, SMEM_SZ);

    int dev = 0, sms = 148;
    cudaGetDevice(&dev);
    cudaDeviceGetAttribute(&sms, cudaDevAttrMultiProcessorCount, dev);
    if (sms > nunits) sms = nunits;

    prep_w1<<<512, 128>>>(Wc, Wp, bp, pre, post, out + (size_t)2 * Brows * 256);
    prep_w2<<<512, 128>>>(Wo, bo);
    fused_main<<<sms, 512, SMEM_SZ>>>(x, out, Brows, nunits);
}

// round 10
// speedup vs baseline: 1.1859x; 1.1859x over previous
#include <cuda_runtime.h>
#include <cuda_fp16.h>
#include <cstdint>

// ============================================================================
// Portable PTX helpers (mma.sync / ldmatrix / cp.async only — no 'a'-gated ops)
// ============================================================================

__device__ __forceinline__ uint32_t smem_to_u32(const void* smem_ptr) {
    uint32_t addr;
    asm("{ .reg .u64 tmp; cvta.to.shared.u64 tmp, %1; cvt.u32.u64 %0, tmp; }"
        : "=r"(addr) : "l"(smem_ptr));
    return addr;
}

__device__ __forceinline__ void cp_async16(uint32_t dst, const void* src) {
    asm volatile("cp.async.cg.shared.global [%0], [%1], 16;"
                 :: "r"(dst), "l"(__cvta_generic_to_global(src)));
}
__device__ __forceinline__ void cp_commit() {
    asm volatile("cp.async.commit_group;" ::: "memory");
}
__device__ __forceinline__ void cp_wait0() {
    asm volatile("cp.async.wait_group 0;" ::: "memory");
}

__device__ __forceinline__ void ldmx4(uint32_t* r, uint32_t addr) {
    asm volatile("ldmatrix.sync.aligned.m8n8.x4.shared.b16 {%0,%1,%2,%3}, [%4];"
                 : "=r"(r[0]), "=r"(r[1]), "=r"(r[2]), "=r"(r[3]) : "r"(addr));
}

__device__ __forceinline__ void mma16816(float* c, const uint32_t* a, const uint32_t* b) {
    asm volatile(
        "mma.sync.aligned.m16n8k16.row.col.f32.f16.f16.f32 "
        "{%0,%1,%2,%3}, {%4,%5,%6,%7}, {%8,%9}, {%0,%1,%2,%3};"
        : "+f"(c[0]), "+f"(c[1]), "+f"(c[2]), "+f"(c[3])
        : "r"(a[0]), "r"(a[1]), "r"(a[2]), "r"(a[3]), "r"(b[0]), "r"(b[1]));
}

// ============================================================================
// Problem constants
// ============================================================================
static constexpr int DIN = 256;    // K
static constexpr int BM  = 128;    // CTA M tile
static constexpr int BN  = 256;    // CTA N tile
static constexpr int BK  = 64;     // K chunk (4 k16 steps)
static constexpr int NCHUNK = DIN / BK;  // 4 (even -> tile-boundary stage reuse safe)

static constexpr int A_STRIDE = 144;   // 64 fp16 (128B) + 16B pad -> conflict-free
static constexpr int B_STRIDE = 528;   // 256 fp16 (512B) + 16B pad -> conflict-free
static constexpr int A_STAGE  = BM * A_STRIDE;   // 18432

// smem layout (dynamic, bytes)
static constexpr int SM_B    = 0;                   // 256 * 528 = 135168 (persistent)
static constexpr int SM_A    = 135168;              // 2 stages * 18432 = 36864
static constexpr int SM_BIAS = 172032;              // 256 floats = 1024
static constexpr int SMEM_SZ = 173056;

// ============================================================================
// Device scratch (no allocation allowed -> __device__ globals)
// ============================================================================
__device__ float  g_bias[512];           // [0:256) combined bias c1, [256:512) out bias c2
__device__ float  g_W1[256 * 256];
__device__ __half g_Bh[512 * 256];       // fused weight, [n][k] row-major, fp16

// ============================================================================
// Prep kernels (measured-good): grid 512 (row x col-half), block 128,
// 8 acc chains, unroll 16.
// ============================================================================

__device__ __forceinline__ float warp_sum(float v) {
#pragma unroll
    for (int o = 16; o > 0; o >>= 1) v += __shfl_xor_sync(0xffffffffu, v, o);
    return v;
}

// Block (o, h): W1[o, h*128 + tid] = sum_i (gate*Wc[o,i]) * Wp[i, col].
// h==0 block also computes c1[o] and (o%32==0) the gate outputs.
__global__ void __launch_bounds__(128, 8)
prep_w1(const float* __restrict__ Wc, const float* __restrict__ Wp,
        const float* __restrict__ bp,
        const float* __restrict__ pre, const float* __restrict__ post,
        float* __restrict__ out_tail) {
    __shared__ float sWc[256];
    __shared__ float sRed[4];
    __shared__ float sGate;
    const int o   = blockIdx.x >> 1;
    const int h   = blockIdx.x & 1;
    const int tid = threadIdx.x;
    const int col = h * 128 + tid;
    const int ko  = o >> 5;

    if (tid < 32) {
        float a = pre[ko * 256 + tid];
        float b = post[ko * 32 + tid];
        float sp = warp_sum(a * a);
        float sq = warp_sum(b * b);
        float np = fmaxf(sqrtf(sp), 1e-12f);
        float nq = fmaxf(sqrtf(sq), 1e-12f);
        float d  = warp_sum((a / np) * (b / nq));
        if (tid == 0) {
            float align = 1.0f / (1.0f + expf(-d));
            float g = (align >= 0.3f) ? align : 0.0f;
            sGate = g;
            if ((o & 31) == 0 && h == 0) {
                out_tail[ko] = g;          // alignments
                out_tail[8 + ko] = 1.0f;   // allocation_mask
            }
        }
    }
    __syncthreads();
    const float g = sGate;
    {
        float w0 = Wc[o * 256 + tid] * g;
        float w1 = Wc[o * 256 + 128 + tid] * g;
        sWc[tid] = w0;
        sWc[128 + tid] = w1;
    }
    __syncthreads();

    float acc[8] = {0.f, 0.f, 0.f, 0.f, 0.f, 0.f, 0.f, 0.f};
#pragma unroll 16
    for (int i = 0; i < 256; ++i)
        acc[i & 7] += sWc[i] * Wp[i * 256 + col];
    float r = ((acc[0] + acc[1]) + (acc[2] + acc[3])) +
              ((acc[4] + acc[5]) + (acc[6] + acc[7]));
    g_W1[o * 256 + col] = r;
    g_Bh[o * 256 + col] = __float2half_rn(r);

    if (h == 0) {
        float p = sWc[tid] * bp[tid] + sWc[128 + tid] * bp[128 + tid];
        p = warp_sum(p);
        if ((tid & 31) == 0) sRed[tid >> 5] = p;
        __syncthreads();
        if (tid == 0)
            g_bias[o] = (sRed[0] + sRed[1]) + (sRed[2] + sRed[3]);
    }
}

// Block (o, h): W2[o, col] = sum_i Wo[o,i] * W1[i, col]; h==0 computes c2[o].
__global__ void __launch_bounds__(128, 8)
prep_w2(const float* __restrict__ Wo, const float* __restrict__ bo) {
    __shared__ float sWo[256];
    __shared__ float sRed[4];
    const int o   = blockIdx.x >> 1;
    const int h   = blockIdx.x & 1;
    const int tid = threadIdx.x;
    const int col = h * 128 + tid;

    sWo[tid]       = Wo[o * 256 + tid];
    sWo[128 + tid] = Wo[o * 256 + 128 + tid];
    __syncthreads();

    float acc[8] = {0.f, 0.f, 0.f, 0.f, 0.f, 0.f, 0.f, 0.f};
#pragma unroll 16
    for (int i = 0; i < 256; ++i)
        acc[i & 7] += sWo[i] * g_W1[i * 256 + col];
    float r = ((acc[0] + acc[1]) + (acc[2] + acc[3])) +
              ((acc[4] + acc[5]) + (acc[6] + acc[7]));
    g_Bh[(256 + o) * 256 + col] = __float2half_rn(r);

    if (h == 0) {
        float p = sWo[tid] * g_bias[tid] + sWo[128 + tid] * g_bias[128 + tid];
        p = warp_sum(p);
        if ((tid & 31) == 0) sRed[tid >> 5] = p;
        __syncthreads();
        if (tid == 0)
            g_bias[256 + o] = (sRed[0] + sRed[1]) + (sRed[2] + sRed[3]) + bo[o];
    }
}

// ============================================================================
// Main fused GEMM (persistent CTAs, nt-split grid): C[131072 x 512] = x @ B^T.
// CTAs [0, split) own nt=0 (combined), [split, G) own nt=1 (out). Both halves
// sweep mt in the same order so the two readers of each x tile run nearly
// concurrently -> x DRAM read once, second read hits L2. B + bias loaded
// exactly ONCE per CTA. Tile body identical to the proven R8 version.
// ============================================================================
__global__ void __launch_bounds__(512, 1)
fused_main(const float* __restrict__ x, float* __restrict__ out,
           int Brows, int ntiles) {
    extern __shared__ char smem[];
    const uint32_t sb = smem_to_u32(smem);
    const int tid  = threadIdx.x;
    const int wid  = tid >> 5, lane = tid & 31;
    const int wm   = wid & 3;               // 4 M-warps of 32 rows
    const int wn   = wid >> 2;              // 4 N-warps of 64 cols

    const int split  = (int)(gridDim.x >> 1);
    const int nt     = (blockIdx.x >= split) ? 1 : 0;
    const int cid    = nt ? ((int)blockIdx.x - split) : (int)blockIdx.x;
    const int stride = nt ? ((int)gridDim.x - split) : split;

    // ---- persistent B tile (256 rows x full K) + bias, loaded once ----
    {
        const __half* Bg = g_Bh + (size_t)nt * BN * DIN;
        const uint32_t bd = sb + SM_B;
#pragma unroll
        for (int i = 0; i < 16; ++i) {
            int idx = tid + 512 * i;            // 8192 x 16B
            int row = idx >> 5, kseg = idx & 31;
            cp_async16(bd + row * B_STRIDE + kseg * 16, Bg + row * DIN + kseg * 8);
        }
        if (tid < 64)
            cp_async16(sb + SM_BIAS + tid * 16, g_bias + nt * BN + tid * 4);
        cp_commit();
    }

    // per-thread x mapping: 4 threads/row, 4 consecutive 16B segs each
    const int prow  = tid >> 2;                  // row 0..127
    const int pseg0 = (tid & 3) * 4;             // segs {0..3},{4..7},{8..11},{12..15}

    const int arow  = wm * 32 + (lane & 15);
    const uint32_t acolb = ((lane >> 4) & 1) * 16;
    const int brow0 = wn * 64 + ((lane & 7) | ((lane >> 4) << 3));
    const uint32_t bcolb = ((lane >> 3) & 1) * 16;

    // epilogue base: nt==0 -> combined block (second Brows*256); nt==1 -> out block
    float* hbase = out + (nt ? (size_t)0 : (size_t)Brows * 256);
    const float* bias_s = (const float*)(smem + SM_BIAS);

    for (int mt = cid; mt < ntiles; mt += stride) {
        const float* xrow = x + (size_t)mt * BM * DIN + prow * DIN + pseg0 * 4;

        float acc[2][8][4];
#pragma unroll
        for (int m = 0; m < 2; m++)
#pragma unroll
            for (int n = 0; n < 8; n++)
#pragma unroll
                for (int k = 0; k < 4; k++) acc[m][n][k] = 0.f;

        float4 pre[4];
#pragma unroll
        for (int j = 0; j < 4; ++j)
            pre[j] = *(const float4*)(xrow + j * 4);

#pragma unroll 1
        for (int c = 0; c < NCHUNK; ++c) {
            const int s = c & 1;

            // ---- convert prefetched fp32 -> fp16, STS to A stage s ----
            {
                char* As = smem + SM_A + s * A_STAGE;
#pragma unroll
                for (int j = 0; j < 4; ++j) {
                    __half h0 = __float2half_rn(pre[j].x), h1 = __float2half_rn(pre[j].y);
                    __half h2 = __float2half_rn(pre[j].z), h3 = __float2half_rn(pre[j].w);
                    uint2 hp;
                    hp.x = (uint32_t)__half_as_ushort(h0) | ((uint32_t)__half_as_ushort(h1) << 16);
                    hp.y = (uint32_t)__half_as_ushort(h2) | ((uint32_t)__half_as_ushort(h3) << 16);
                    *(uint2*)(As + prow * A_STRIDE + (pseg0 + j) * 8) = hp;
                }
            }
            if (c == 0) cp_wait0();   // B/bias resident (no-op after first tile)
            __syncthreads();

            // ---- prefetch next chunk (LDG in flight under 64 MMAs) ----
            if (c + 1 < NCHUNK) {
#pragma unroll
                for (int j = 0; j < 4; ++j)
                    pre[j] = *(const float4*)(xrow + (c + 1) * BK + j * 4);
            }

            // ---- 4 k16 steps of MMA ----
            const uint32_t abase = sb + SM_A + s * A_STAGE;
            const uint32_t bks   = sb + SM_B + (uint32_t)(c * 128);
#pragma unroll
            for (int ks = 0; ks < 4; ++ks) {
                uint32_t af[2][4], bf[4][4];
#pragma unroll
                for (int m = 0; m < 2; ++m)
                    ldmx4(af[m], abase + (uint32_t)((arow + m * 16) * A_STRIDE) + acolb + ks * 32);
#pragma unroll
                for (int p = 0; p < 4; ++p)
                    ldmx4(bf[p], bks + (uint32_t)((brow0 + p * 16) * B_STRIDE) + bcolb + ks * 32);
#pragma unroll
                for (int m = 0; m < 2; ++m)
#pragma unroll
                    for (int n = 0; n < 8; ++n)
                        mma16816(acc[m][n], af[m], &bf[n >> 1][(n & 1) * 2]);
            }
        }

        // ---- epilogue: add fused bias (smem), write this CTA's output half ----
#pragma unroll
        for (int m = 0; m < 2; ++m) {
            const int row = mt * BM + wm * 32 + m * 16 + (lane >> 2);
            float* rp = hbase + (size_t)row * 256;
#pragma unroll
            for (int n = 0; n < 8; ++n) {
                const int ln = wn * 64 + n * 8 + (lane & 3) * 2;   // 0..255 column
                const float b0 = bias_s[ln], b1 = bias_s[ln + 1];
                *(float2*)(rp + ln)           = make_float2(acc[m][n][0] + b0, acc[m][n][1] + b1);
                *(float2*)(rp + ln + 8 * 256) = make_float2(acc[m][n][2] + b0, acc[m][n][3] + b1);
            }
        }
    }
}

// ============================================================================
// kernel_launch
// ============================================================================
extern "C" void kernel_launch(void* const* d_in, const int* in_sizes, int n_in,
                              void* d_out, int out_size) {
    const float* x    = (const float*)d_in[0];
    const float* Wp   = (const float*)d_in[1];
    const float* bp   = (const float*)d_in[2];
    const float* pre  = (const float*)d_in[3];
    const float* post = (const float*)d_in[4];
    const float* Wc   = (const float*)d_in[5];
    const float* Wo   = (const float*)d_in[6];
    const float* bo   = (const float*)d_in[7];
    float* out = (float*)d_out;
    const int Brows  = in_sizes[0] / 256;     // 131072
    const int ntiles = Brows / BM;            // 1024

    cudaFuncSetAttribute(fused_main, cudaFuncAttributeMaxDynamicSharedMemorySize, SMEM_SZ);

    int dev = 0, sms = 148;
    cudaGetDevice(&dev);
    cudaDeviceGetAttribute(&sms, cudaDevAttrMultiProcessorCount, dev);
    int grid = sms & ~1;                      // even split across the two N-halves
    if (grid > 2 * ntiles) grid = 2 * ntiles;

    prep_w1<<<512, 128>>>(Wc, Wp, bp, pre, post, out + (size_t)2 * Brows * 256);
    prep_w2<<<512, 128>>>(Wo, bo);
    fused_main<<<grid, 512, SMEM_SZ>>>(x, out, Brows, ntiles);
}

// round 11
// speedup vs baseline: 1.1905x; 1.0039x over previous
#include <cuda_runtime.h>
#include <cuda_fp16.h>
#include <cstdint>

// ============================================================================
// Portable PTX helpers (mma.sync / ldmatrix / cp.async only — no 'a'-gated ops)
// ============================================================================

__device__ __forceinline__ uint32_t smem_to_u32(const void* smem_ptr) {
    uint32_t addr;
    asm("{ .reg .u64 tmp; cvta.to.shared.u64 tmp, %1; cvt.u32.u64 %0, tmp; }"
        : "=r"(addr) : "l"(smem_ptr));
    return addr;
}

__device__ __forceinline__ void cp_async16(uint32_t dst, const void* src) {
    asm volatile("cp.async.cg.shared.global [%0], [%1], 16;"
                 :: "r"(dst), "l"(__cvta_generic_to_global(src)));
}
__device__ __forceinline__ void cp_commit() {
    asm volatile("cp.async.commit_group;" ::: "memory");
}
__device__ __forceinline__ void cp_wait0() {
    asm volatile("cp.async.wait_group 0;" ::: "memory");
}

__device__ __forceinline__ void ldmx4(uint32_t* r, uint32_t addr) {
    asm volatile("ldmatrix.sync.aligned.m8n8.x4.shared.b16 {%0,%1,%2,%3}, [%4];"
                 : "=r"(r[0]), "=r"(r[1]), "=r"(r[2]), "=r"(r[3]) : "r"(addr));
}

__device__ __forceinline__ void mma16816(float* c, const uint32_t* a, const uint32_t* b) {
    asm volatile(
        "mma.sync.aligned.m16n8k16.row.col.f32.f16.f16.f32 "
        "{%0,%1,%2,%3}, {%4,%5,%6,%7}, {%8,%9}, {%0,%1,%2,%3};"
        : "+f"(c[0]), "+f"(c[1]), "+f"(c[2]), "+f"(c[3])
        : "r"(a[0]), "r"(a[1]), "r"(a[2]), "r"(a[3]), "r"(b[0]), "r"(b[1]));
}

// ============================================================================
// Problem constants
// ============================================================================
static constexpr int DIN = 256;    // K
static constexpr int BM  = 128;    // CTA M tile
static constexpr int BN  = 256;    // CTA N tile
static constexpr int BK  = 64;     // K chunk (4 k16 steps)
static constexpr int NCHUNK = DIN / BK;  // 4 (even -> tile-boundary stage reuse safe)

static constexpr int A_STRIDE = 144;   // 64 fp16 (128B) + 16B pad -> conflict-free
static constexpr int B_STRIDE = 528;   // 256 fp16 (512B) + 16B pad -> conflict-free
static constexpr int A_STAGE  = BM * A_STRIDE;   // 18432

// smem layout (dynamic, bytes)
static constexpr int SM_B    = 0;                   // 256 * 528 = 135168 (persistent)
static constexpr int SM_A    = 135168;              // 2 stages * 18432 = 36864
static constexpr int SM_BIAS = 172032;              // 256 floats = 1024
static constexpr int SMEM_SZ = 173056;

// ============================================================================
// Device scratch (no allocation allowed -> __device__ globals)
// ============================================================================
__device__ float  g_bias[512];           // [0:256) combined bias c1, [256:512) out bias c2
__device__ float  g_W1[256 * 256];
__device__ __half g_Bh[512 * 256];       // fused weight, [n][k] row-major, fp16

// ============================================================================
// Prep kernels (measured-good): grid 512 (row x col-half), block 128,
// 8 acc chains, unroll 16.
// ============================================================================

__device__ __forceinline__ float warp_sum(float v) {
#pragma unroll
    for (int o = 16; o > 0; o >>= 1) v += __shfl_xor_sync(0xffffffffu, v, o);
    return v;
}

// Block (o, h): W1[o, h*128 + tid] = sum_i (gate*Wc[o,i]) * Wp[i, col].
// h==0 block also computes c1[o] and (o%32==0) the gate outputs.
__global__ void __launch_bounds__(128, 8)
prep_w1(const float* __restrict__ Wc, const float* __restrict__ Wp,
        const float* __restrict__ bp,
        const float* __restrict__ pre, const float* __restrict__ post,
        float* __restrict__ out_tail) {
    __shared__ float sWc[256];
    __shared__ float sRed[4];
    __shared__ float sGate;
    const int o   = blockIdx.x >> 1;
    const int h   = blockIdx.x & 1;
    const int tid = threadIdx.x;
    const int col = h * 128 + tid;
    const int ko  = o >> 5;

    if (tid < 32) {
        float a = pre[ko * 256 + tid];
        float b = post[ko * 32 + tid];
        float sp = warp_sum(a * a);
        float sq = warp_sum(b * b);
        float np = fmaxf(sqrtf(sp), 1e-12f);
        float nq = fmaxf(sqrtf(sq), 1e-12f);
        float d  = warp_sum((a / np) * (b / nq));
        if (tid == 0) {
            float align = 1.0f / (1.0f + expf(-d));
            float g = (align >= 0.3f) ? align : 0.0f;
            sGate = g;
            if ((o & 31) == 0 && h == 0) {
                out_tail[ko] = g;          // alignments
                out_tail[8 + ko] = 1.0f;   // allocation_mask
            }
        }
    }
    __syncthreads();
    const float g = sGate;
    {
        float w0 = Wc[o * 256 + tid] * g;
        float w1 = Wc[o * 256 + 128 + tid] * g;
        sWc[tid] = w0;
        sWc[128 + tid] = w1;
    }
    __syncthreads();

    float acc[8] = {0.f, 0.f, 0.f, 0.f, 0.f, 0.f, 0.f, 0.f};
#pragma unroll 16
    for (int i = 0; i < 256; ++i)
        acc[i & 7] += sWc[i] * Wp[i * 256 + col];
    float r = ((acc[0] + acc[1]) + (acc[2] + acc[3])) +
              ((acc[4] + acc[5]) + (acc[6] + acc[7]));
    g_W1[o * 256 + col] = r;
    g_Bh[o * 256 + col] = __float2half_rn(r);

    if (h == 0) {
        float p = sWc[tid] * bp[tid] + sWc[128 + tid] * bp[128 + tid];
        p = warp_sum(p);
        if ((tid & 31) == 0) sRed[tid >> 5] = p;
        __syncthreads();
        if (tid == 0)
            g_bias[o] = (sRed[0] + sRed[1]) + (sRed[2] + sRed[3]);
    }
}

// Block (o, h): W2[o, col] = sum_i Wo[o,i] * W1[i, col]; h==0 computes c2[o].
__global__ void __launch_bounds__(128, 8)
prep_w2(const float* __restrict__ Wo, const float* __restrict__ bo) {
    __shared__ float sWo[256];
    __shared__ float sRed[4];
    const int o   = blockIdx.x >> 1;
    const int h   = blockIdx.x & 1;
    const int tid = threadIdx.x;
    const int col = h * 128 + tid;

    sWo[tid]       = Wo[o * 256 + tid];
    sWo[128 + tid] = Wo[o * 256 + 128 + tid];
    __syncthreads();

    float acc[8] = {0.f, 0.f, 0.f, 0.f, 0.f, 0.f, 0.f, 0.f};
#pragma unroll 16
    for (int i = 0; i < 256; ++i)
        acc[i & 7] += sWo[i] * g_W1[i * 256 + col];
    float r = ((acc[0] + acc[1]) + (acc[2] + acc[3])) +
              ((acc[4] + acc[5]) + (acc[6] + acc[7]));
    g_Bh[(256 + o) * 256 + col] = __float2half_rn(r);

    if (h == 0) {
        float p = sWo[tid] * g_bias[tid] + sWo[128 + tid] * g_bias[128 + tid];
        p = warp_sum(p);
        if ((tid & 31) == 0) sRed[tid >> 5] = p;
        __syncthreads();
        if (tid == 0)
            g_bias[256 + o] = (sRed[0] + sRed[1]) + (sRed[2] + sRed[3]) + bo[o];
    }
}

// ============================================================================
// Main fused GEMM (persistent CTAs, nt-split grid): C[131072 x 512] = x @ B^T.
// CTAs [0, split) own nt=0 (combined), [split, G) own nt=1 (out). Both halves
// sweep mt in the same order so the two readers of each x tile run nearly
// concurrently -> x DRAM read once, second read hits L2. B + bias loaded
// exactly ONCE per CTA. Tile body identical to the proven R8 version.
// ============================================================================
__global__ void __launch_bounds__(512, 1)
fused_main(const float* __restrict__ x, float* __restrict__ out,
           int Brows, int ntiles) {
    extern __shared__ char smem[];
    const uint32_t sb = smem_to_u32(smem);
    const int tid  = threadIdx.x;
    const int wid  = tid >> 5, lane = tid & 31;
    const int wm   = wid & 3;               // 4 M-warps of 32 rows
    const int wn   = wid >> 2;              // 4 N-warps of 64 cols

    const int split  = (int)(gridDim.x >> 1);
    const int nt     = (blockIdx.x >= split) ? 1 : 0;
    const int cid    = nt ? ((int)blockIdx.x - split) : (int)blockIdx.x;
    const int stride = nt ? ((int)gridDim.x - split) : split;

    // ---- persistent B tile (256 rows x full K) + bias, loaded once ----
    {
        const __half* Bg = g_Bh + (size_t)nt * BN * DIN;
        const uint32_t bd = sb + SM_B;
#pragma unroll
        for (int i = 0; i < 16; ++i) {
            int idx = tid + 512 * i;            // 8192 x 16B
            int row = idx >> 5, kseg = idx & 31;
            cp_async16(bd + row * B_STRIDE + kseg * 16, Bg + row * DIN + kseg * 8);
        }
        if (tid < 64)
            cp_async16(sb + SM_BIAS + tid * 16, g_bias + nt * BN + tid * 4);
        cp_commit();
    }

    // per-thread x mapping: 4 threads/row, 4 consecutive 16B segs each
    const int prow  = tid >> 2;                  // row 0..127
    const int pseg0 = (tid & 3) * 4;             // segs {0..3},{4..7},{8..11},{12..15}

    const int arow  = wm * 32 + (lane & 15);
    const uint32_t acolb = ((lane >> 4) & 1) * 16;
    const int brow0 = wn * 64 + ((lane & 7) | ((lane >> 4) << 3));
    const uint32_t bcolb = ((lane >> 3) & 1) * 16;

    // epilogue base: nt==0 -> combined block (second Brows*256); nt==1 -> out block
    float* hbase = out + (nt ? (size_t)0 : (size_t)Brows * 256);
    const float* bias_s = (const float*)(smem + SM_BIAS);

    for (int mt = cid; mt < ntiles; mt += stride) {
        const float* xrow = x + (size_t)mt * BM * DIN + prow * DIN + pseg0 * 4;

        float acc[2][8][4];
#pragma unroll
        for (int m = 0; m < 2; m++)
#pragma unroll
            for (int n = 0; n < 8; n++)
#pragma unroll
                for (int k = 0; k < 4; k++) acc[m][n][k] = 0.f;

        float4 pre[4];
#pragma unroll
        for (int j = 0; j < 4; ++j)
            pre[j] = *(const float4*)(xrow + j * 4);

#pragma unroll 1
        for (int c = 0; c < NCHUNK; ++c) {
            const int s = c & 1;

            // ---- convert prefetched fp32 -> fp16, STS to A stage s ----
            {
                char* As = smem + SM_A + s * A_STAGE;
#pragma unroll
                for (int j = 0; j < 4; ++j) {
                    __half h0 = __float2half_rn(pre[j].x), h1 = __float2half_rn(pre[j].y);
                    __half h2 = __float2half_rn(pre[j].z), h3 = __float2half_rn(pre[j].w);
                    uint2 hp;
                    hp.x = (uint32_t)__half_as_ushort(h0) | ((uint32_t)__half_as_ushort(h1) << 16);
                    hp.y = (uint32_t)__half_as_ushort(h2) | ((uint32_t)__half_as_ushort(h3) << 16);
                    *(uint2*)(As + prow * A_STRIDE + (pseg0 + j) * 8) = hp;
                }
            }
            if (c == 0) cp_wait0();   // B/bias resident (no-op after first tile)
            __syncthreads();

            // ---- prefetch next chunk (LDG in flight under 64 MMAs) ----
            if (c + 1 < NCHUNK) {
#pragma unroll
                for (int j = 0; j < 4; ++j)
                    pre[j] = *(const float4*)(xrow + (c + 1) * BK + j * 4);
            }

            // ---- 4 k16 steps of MMA ----
            const uint32_t abase = sb + SM_A + s * A_STAGE;
            const uint32_t bks   = sb + SM_B + (uint32_t)(c * 128);
#pragma unroll
            for (int ks = 0; ks < 4; ++ks) {
                uint32_t af[2][4], bf[4][4];
#pragma unroll
                for (int m = 0; m < 2; ++m)
                    ldmx4(af[m], abase + (uint32_t)((arow + m * 16) * A_STRIDE) + acolb + ks * 32);
#pragma unroll
                for (int p = 0; p < 4; ++p)
                    ldmx4(bf[p], bks + (uint32_t)((brow0 + p * 16) * B_STRIDE) + bcolb + ks * 32);
#pragma unroll
                for (int m = 0; m < 2; ++m)
#pragma unroll
                    for (int n = 0; n < 8; ++n)
                        mma16816(acc[m][n], af[m], &bf[n >> 1][(n & 1) * 2]);
            }
        }

        // ---- epilogue: add fused bias (smem), write this CTA's output half ----
#pragma unroll
        for (int m = 0; m < 2; ++m) {
            const int row = mt * BM + wm * 32 + m * 16 + (lane >> 2);
            float* rp = hbase + (size_t)row * 256;
#pragma unroll
            for (int n = 0; n < 8; ++n) {
                const int ln = wn * 64 + n * 8 + (lane & 3) * 2;   // 0..255 column
                const float b0 = bias_s[ln], b1 = bias_s[ln + 1];
                *(float2*)(rp + ln)           = make_float2(acc[m][n][0] + b0, acc[m][n][1] + b1);
                *(float2*)(rp + ln + 8 * 256) = make_float2(acc[m][n][2] + b0, acc[m][n][3] + b1);
            }
        }
    }
}

// ============================================================================
// kernel_launch
// ============================================================================
extern "C" void kernel_launch(void* const* d_in, const int* in_sizes, int n_in,
                              void* d_out, int out_size) {
    const float* x    = (const float*)d_in[0];
    const float* Wp   = (const float*)d_in[1];
    const float* bp   = (const float*)d_in[2];
    const float* pre  = (const float*)d_in[3];
    const float* post = (const float*)d_in[4];
    const float* Wc   = (const float*)d_in[5];
    const float* Wo   = (const float*)d_in[6];
    const float* bo   = (const float*)d_in[7];
    float* out = (float*)d_out;
    const int Brows  = in_sizes[0] / 256;     // 131072
    const int ntiles = Brows / BM;            // 1024

    cudaFuncSetAttribute(fused_main, cudaFuncAttributeMaxDynamicSharedMemorySize, SMEM_SZ);

    int dev = 0, sms = 148;
    cudaGetDevice(&dev);
    cudaDeviceGetAttribute(&sms, cudaDevAttrMultiProcessorCount, dev);
    int grid = sms & ~1;                      // even split across the two N-halves
    if (grid > 2 * ntiles) grid = 2 * ntiles;

    prep_w1<<<512, 128>>>(Wc, Wp, bp, pre, post, out + (size_t)2 * Brows * 256);
    prep_w2<<<512, 128>>>(Wo, bo);
    fused_main<<<grid, 512, SMEM_SZ>>>(x, out, Brows, ntiles);
}

// round 12
// speedup vs baseline: 1.2478x; 1.0481x over previous
#include <cuda_runtime.h>
#include <cuda_fp16.h>
#include <cstdint>

// ============================================================================
// Portable PTX helpers (mma.sync / ldmatrix / cp.async only — no 'a'-gated ops)
// ============================================================================

__device__ __forceinline__ uint32_t smem_to_u32(const void* smem_ptr) {
    uint32_t addr;
    asm("{ .reg .u64 tmp; cvta.to.shared.u64 tmp, %1; cvt.u32.u64 %0, tmp; }"
        : "=r"(addr) : "l"(smem_ptr));
    return addr;
}

__device__ __forceinline__ void cp_async16(uint32_t dst, const void* src) {
    asm volatile("cp.async.cg.shared.global [%0], [%1], 16;"
                 :: "r"(dst), "l"(__cvta_generic_to_global(src)));
}
__device__ __forceinline__ void cp_commit() {
    asm volatile("cp.async.commit_group;" ::: "memory");
}
__device__ __forceinline__ void cp_wait0() {
    asm volatile("cp.async.wait_group 0;" ::: "memory");
}

__device__ __forceinline__ void ldmx4(uint32_t* r, uint32_t addr) {
    asm volatile("ldmatrix.sync.aligned.m8n8.x4.shared.b16 {%0,%1,%2,%3}, [%4];"
                 : "=r"(r[0]), "=r"(r[1]), "=r"(r[2]), "=r"(r[3]) : "r"(addr));
}

__device__ __forceinline__ void mma16816(float* c, const uint32_t* a, const uint32_t* b) {
    asm volatile(
        "mma.sync.aligned.m16n8k16.row.col.f32.f16.f16.f32 "
        "{%0,%1,%2,%3}, {%4,%5,%6,%7}, {%8,%9}, {%0,%1,%2,%3};"
        : "+f"(c[0]), "+f"(c[1]), "+f"(c[2]), "+f"(c[3])
        : "r"(a[0]), "r"(a[1]), "r"(a[2]), "r"(a[3]), "r"(b[0]), "r"(b[1]));
}

// packed fp32x2 -> fp16x2 convert (round-to-nearest, identical to __float2half_rn)
__device__ __forceinline__ uint32_t cvt2h(float lo, float hi) {
    uint32_t r;
    asm("cvt.rn.f16x2.f32 %0, %1, %2;" : "=r"(r) : "f"(hi), "f"(lo));
    return r;
}

// ============================================================================
// Problem constants
// ============================================================================
static constexpr int DIN = 256;    // K
static constexpr int BM  = 128;    // CTA M tile
static constexpr int BN  = 256;    // CTA N tile
static constexpr int BK  = 64;     // K chunk (4 k16 steps)
static constexpr int NCHUNK = DIN / BK;  // 4 (even -> tile-boundary stage reuse safe)

static constexpr int A_STRIDE = 144;   // 64 fp16 (128B) + 16B pad -> conflict-free
static constexpr int B_STRIDE = 528;   // 256 fp16 (512B) + 16B pad -> conflict-free
static constexpr int A_STAGE  = BM * A_STRIDE;   // 18432

// smem layout (dynamic, bytes)
static constexpr int SM_B    = 0;                   // 256 * 528 = 135168 (persistent)
static constexpr int SM_A    = 135168;              // 2 stages * 18432 = 36864
static constexpr int SM_BIAS = 172032;              // 256 floats = 1024
static constexpr int SMEM_SZ = 173056;

// ============================================================================
// Device scratch (no allocation allowed -> __device__ globals)
// ============================================================================
__device__ float  g_bias[512];           // [0:256) combined bias c1, [256:512) out bias c2
__device__ float  g_W1[256 * 256];
__device__ __half g_Bh[512 * 256];       // fused weight, [n][k] row-major, fp16

// ============================================================================
// Prep kernels (measured-good): grid 512 (row x col-half), block 128,
// 8 acc chains, unroll 16.
// ============================================================================

__device__ __forceinline__ float warp_sum(float v) {
#pragma unroll
    for (int o = 16; o > 0; o >>= 1) v += __shfl_xor_sync(0xffffffffu, v, o);
    return v;
}

// Block (o, h): W1[o, h*128 + tid] = sum_i (gate*Wc[o,i]) * Wp[i, col].
// h==0 block also computes c1[o] and (o%32==0) the gate outputs.
__global__ void __launch_bounds__(128, 8)
prep_w1(const float* __restrict__ Wc, const float* __restrict__ Wp,
        const float* __restrict__ bp,
        const float* __restrict__ pre, const float* __restrict__ post,
        float* __restrict__ out_tail) {
    __shared__ float sWc[256];
    __shared__ float sRed[4];
    __shared__ float sGate;
    const int o   = blockIdx.x >> 1;
    const int h   = blockIdx.x & 1;
    const int tid = threadIdx.x;
    const int col = h * 128 + tid;
    const int ko  = o >> 5;

    if (tid < 32) {
        float a = pre[ko * 256 + tid];
        float b = post[ko * 32 + tid];
        float sp = warp_sum(a * a);
        float sq = warp_sum(b * b);
        float np = fmaxf(sqrtf(sp), 1e-12f);
        float nq = fmaxf(sqrtf(sq), 1e-12f);
        float d  = warp_sum((a / np) * (b / nq));
        if (tid == 0) {
            float align = 1.0f / (1.0f + expf(-d));
            float g = (align >= 0.3f) ? align : 0.0f;
            sGate = g;
            if ((o & 31) == 0 && h == 0) {
                out_tail[ko] = g;          // alignments
                out_tail[8 + ko] = 1.0f;   // allocation_mask
            }
        }
    }
    __syncthreads();
    const float g = sGate;
    {
        float w0 = Wc[o * 256 + tid] * g;
        float w1 = Wc[o * 256 + 128 + tid] * g;
        sWc[tid] = w0;
        sWc[128 + tid] = w1;
    }
    __syncthreads();

    float acc[8] = {0.f, 0.f, 0.f, 0.f, 0.f, 0.f, 0.f, 0.f};
#pragma unroll 16
    for (int i = 0; i < 256; ++i)
        acc[i & 7] += sWc[i] * Wp[i * 256 + col];
    float r = ((acc[0] + acc[1]) + (acc[2] + acc[3])) +
              ((acc[4] + acc[5]) + (acc[6] + acc[7]));
    g_W1[o * 256 + col] = r;
    g_Bh[o * 256 + col] = __float2half_rn(r);

    if (h == 0) {
        float p = sWc[tid] * bp[tid] + sWc[128 + tid] * bp[128 + tid];
        p = warp_sum(p);
        if ((tid & 31) == 0) sRed[tid >> 5] = p;
        __syncthreads();
        if (tid == 0)
            g_bias[o] = (sRed[0] + sRed[1]) + (sRed[2] + sRed[3]);
    }
}

// Block (o, h): W2[o, col] = sum_i Wo[o,i] * W1[i, col]; h==0 computes c2[o].
__global__ void __launch_bounds__(128, 8)
prep_w2(const float* __restrict__ Wo, const float* __restrict__ bo) {
    __shared__ float sWo[256];
    __shared__ float sRed[4];
    const int o   = blockIdx.x >> 1;
    const int h   = blockIdx.x & 1;
    const int tid = threadIdx.x;
    const int col = h * 128 + tid;

    sWo[tid]       = Wo[o * 256 + tid];
    sWo[128 + tid] = Wo[o * 256 + 128 + tid];
    __syncthreads();

    float acc[8] = {0.f, 0.f, 0.f, 0.f, 0.f, 0.f, 0.f, 0.f};
#pragma unroll 16
    for (int i = 0; i < 256; ++i)
        acc[i & 7] += sWo[i] * g_W1[i * 256 + col];
    float r = ((acc[0] + acc[1]) + (acc[2] + acc[3])) +
              ((acc[4] + acc[5]) + (acc[6] + acc[7]));
    g_Bh[(256 + o) * 256 + col] = __float2half_rn(r);

    if (h == 0) {
        float p = sWo[tid] * g_bias[tid] + sWo[128 + tid] * g_bias[128 + tid];
        p = warp_sum(p);
        if ((tid & 31) == 0) sRed[tid >> 5] = p;
        __syncthreads();
        if (tid == 0)
            g_bias[256 + o] = (sRed[0] + sRed[1]) + (sRed[2] + sRed[3]) + bo[o];
    }
}

// ============================================================================
// Main fused GEMM (persistent CTAs, nt-split grid, cross-tile prefetch):
// C[131072 x 512] = x @ B^T. CTAs [0, split) own nt=0 (combined), [split, G)
// own nt=1 (out); both halves sweep mt in lockstep for x L2 reuse. B + bias
// loaded exactly once per CTA. Within a tile: STS(chunk c) / sync /
// prefetch(c+1 or next tile's chunk 0) / 64 MMAs. The next-tile prefetch
// flies under the last chunk's MMAs + the epilogue.
// ============================================================================
__global__ void __launch_bounds__(512, 1)
fused_main(const float* __restrict__ x, float* __restrict__ out,
           int Brows, int ntiles) {
    extern __shared__ char smem[];
    const uint32_t sb = smem_to_u32(smem);
    const int tid  = threadIdx.x;
    const int wid  = tid >> 5, lane = tid & 31;
    const int wm   = wid & 3;               // 4 M-warps of 32 rows
    const int wn   = wid >> 2;              // 4 N-warps of 64 cols

    const int split  = (int)(gridDim.x >> 1);
    const int nt     = (blockIdx.x >= split) ? 1 : 0;
    const int cid    = nt ? ((int)blockIdx.x - split) : (int)blockIdx.x;
    const int stride = nt ? ((int)gridDim.x - split) : split;

    // ---- persistent B tile (256 rows x full K) + bias, loaded once ----
    {
        const __half* Bg = g_Bh + (size_t)nt * BN * DIN;
        const uint32_t bd = sb + SM_B;
#pragma unroll
        for (int i = 0; i < 16; ++i) {
            int idx = tid + 512 * i;            // 8192 x 16B
            int row = idx >> 5, kseg = idx & 31;
            cp_async16(bd + row * B_STRIDE + kseg * 16, Bg + row * DIN + kseg * 8);
        }
        if (tid < 64)
            cp_async16(sb + SM_BIAS + tid * 16, g_bias + nt * BN + tid * 4);
        cp_commit();
    }

    // per-thread x mapping: 4 threads/row, 4 consecutive 16B segs each
    const int prow  = tid >> 2;                  // row 0..127
    const int pseg0 = (tid & 3) * 4;             // segs {0..3},{4..7},{8..11},{12..15}
    const size_t tile_step = (size_t)stride * BM * DIN;

    const int arow  = wm * 32 + (lane & 15);
    const uint32_t acolb = ((lane >> 4) & 1) * 16;
    const int brow0 = wn * 64 + ((lane & 7) | ((lane >> 4) << 3));
    const uint32_t bcolb = ((lane >> 3) & 1) * 16;

    // epilogue base: nt==0 -> combined block (second Brows*256); nt==1 -> out block
    float* hbase = out + (nt ? (size_t)0 : (size_t)Brows * 256);
    const float* bias_s = (const float*)(smem + SM_BIAS);

    // initial x prefetch (tile cid, chunk 0), then wait for B residency once
    const float* xrow0 = x + (size_t)cid * BM * DIN + prow * DIN + pseg0 * 4;
    float4 pre[4];
    if (cid < ntiles) {
#pragma unroll
        for (int j = 0; j < 4; ++j)
            pre[j] = *(const float4*)(xrow0 + j * 4);
    }
    cp_wait0();

    for (int mt = cid; mt < ntiles; mt += stride) {
        const float* xrow = x + (size_t)mt * BM * DIN + prow * DIN + pseg0 * 4;

        float acc[2][8][4];
#pragma unroll
        for (int m = 0; m < 2; m++)
#pragma unroll
            for (int n = 0; n < 8; n++)
#pragma unroll
                for (int k = 0; k < 4; k++) acc[m][n][k] = 0.f;

#pragma unroll 1
        for (int c = 0; c < NCHUNK; ++c) {
            const int s = c & 1;

            // ---- convert prefetched fp32 -> fp16 (packed cvt), STS stage s ----
            {
                char* As = smem + SM_A + s * A_STAGE;
#pragma unroll
                for (int j = 0; j < 4; ++j) {
                    uint2 hp;
                    hp.x = cvt2h(pre[j].x, pre[j].y);
                    hp.y = cvt2h(pre[j].z, pre[j].w);
                    *(uint2*)(As + prow * A_STRIDE + (pseg0 + j) * 8) = hp;
                }
            }
            __syncthreads();

            // ---- prefetch chunk c+1, or next tile's chunk 0 ----
            if (c + 1 < NCHUNK) {
#pragma unroll
                for (int j = 0; j < 4; ++j)
                    pre[j] = *(const float4*)(xrow + (c + 1) * BK + j * 4);
            } else if (mt + stride < ntiles) {
#pragma unroll
                for (int j = 0; j < 4; ++j)
                    pre[j] = *(const float4*)(xrow + tile_step + j * 4);
            }

            // ---- 4 k16 steps of MMA ----
            const uint32_t abase = sb + SM_A + s * A_STAGE;
            const uint32_t bks   = sb + SM_B + (uint32_t)(c * 128);
#pragma unroll
            for (int ks = 0; ks < 4; ++ks) {
                uint32_t af[2][4], bf[4][4];
#pragma unroll
                for (int m = 0; m < 2; ++m)
                    ldmx4(af[m], abase + (uint32_t)((arow + m * 16) * A_STRIDE) + acolb + ks * 32);
#pragma unroll
                for (int p = 0; p < 4; ++p)
                    ldmx4(bf[p], bks + (uint32_t)((brow0 + p * 16) * B_STRIDE) + bcolb + ks * 32);
#pragma unroll
                for (int m = 0; m < 2; ++m)
#pragma unroll
                    for (int n = 0; n < 8; ++n)
                        mma16816(acc[m][n], af[m], &bf[n >> 1][(n & 1) * 2]);
            }
        }

        // ---- epilogue: add fused bias (smem), write this CTA's output half ----
#pragma unroll
        for (int m = 0; m < 2; ++m) {
            const int row = mt * BM + wm * 32 + m * 16 + (lane >> 2);
            float* rp = hbase + (size_t)row * 256;
#pragma unroll
            for (int n = 0; n < 8; ++n) {
                const int ln = wn * 64 + n * 8 + (lane & 3) * 2;   // 0..255 column
                const float b0 = bias_s[ln], b1 = bias_s[ln + 1];
                *(float2*)(rp + ln)           = make_float2(acc[m][n][0] + b0, acc[m][n][1] + b1);
                *(float2*)(rp + ln + 8 * 256) = make_float2(acc[m][n][2] + b0, acc[m][n][3] + b1);
            }
        }
    }
}

// ============================================================================
// kernel_launch
// ============================================================================
extern "C" void kernel_launch(void* const* d_in, const int* in_sizes, int n_in,
                              void* d_out, int out_size) {
    const float* x    = (const float*)d_in[0];
    const float* Wp   = (const float*)d_in[1];
    const float* bp   = (const float*)d_in[2];
    const float* pre  = (const float*)d_in[3];
    const float* post = (const float*)d_in[4];
    const float* Wc   = (const float*)d_in[5];
    const float* Wo   = (const float*)d_in[6];
    const float* bo   = (const float*)d_in[7];
    float* out = (float*)d_out;
    const int Brows  = in_sizes[0] / 256;     // 131072
    const int ntiles = Brows / BM;            // 1024

    cudaFuncSetAttribute(fused_main, cudaFuncAttributeMaxDynamicSharedMemorySize, SMEM_SZ);

    int dev = 0, sms = 148;
    cudaGetDevice(&dev);
    cudaDeviceGetAttribute(&sms, cudaDevAttrMultiProcessorCount, dev);
    int grid = sms & ~1;                      // even split across the two N-halves
    if (grid > 2 * ntiles) grid = 2 * ntiles;

    prep_w1<<<512, 128>>>(Wc, Wp, bp, pre, post, out + (size_t)2 * Brows * 256);
    prep_w2<<<512, 128>>>(Wo, bo);
    fused_main<<<grid, 512, SMEM_SZ>>>(x, out, Brows, ntiles);
}

// round 13
// speedup vs baseline: 1.2842x; 1.0291x over previous
#include <cuda_runtime.h>
#include <cuda_fp16.h>
#include <cstdint>

// ============================================================================
// Portable PTX helpers (mma.sync / ldmatrix / cp.async only — no 'a'-gated ops)
// ============================================================================

__device__ __forceinline__ uint32_t smem_to_u32(const void* smem_ptr) {
    uint32_t addr;
    asm("{ .reg .u64 tmp; cvta.to.shared.u64 tmp, %1; cvt.u32.u64 %0, tmp; }"
        : "=r"(addr) : "l"(smem_ptr));
    return addr;
}

__device__ __forceinline__ void cp_async16(uint32_t dst, const void* src) {
    asm volatile("cp.async.cg.shared.global [%0], [%1], 16;"
                 :: "r"(dst), "l"(__cvta_generic_to_global(src)));
}
__device__ __forceinline__ void cp_commit() {
    asm volatile("cp.async.commit_group;" ::: "memory");
}
__device__ __forceinline__ void cp_wait0() {
    asm volatile("cp.async.wait_group 0;" ::: "memory");
}

__device__ __forceinline__ void ldmx4(uint32_t* r, uint32_t addr) {
    asm volatile("ldmatrix.sync.aligned.m8n8.x4.shared.b16 {%0,%1,%2,%3}, [%4];"
                 : "=r"(r[0]), "=r"(r[1]), "=r"(r[2]), "=r"(r[3]) : "r"(addr));
}

__device__ __forceinline__ void mma16816(float* c, const uint32_t* a, const uint32_t* b) {
    asm volatile(
        "mma.sync.aligned.m16n8k16.row.col.f32.f16.f16.f32 "
        "{%0,%1,%2,%3}, {%4,%5,%6,%7}, {%8,%9}, {%0,%1,%2,%3};"
        : "+f"(c[0]), "+f"(c[1]), "+f"(c[2]), "+f"(c[3])
        : "r"(a[0]), "r"(a[1]), "r"(a[2]), "r"(a[3]), "r"(b[0]), "r"(b[1]));
}

// packed fp32x2 -> fp16x2 convert (round-to-nearest, identical to __float2half_rn)
__device__ __forceinline__ uint32_t cvt2h(float lo, float hi) {
    uint32_t r;
    asm("cvt.rn.f16x2.f32 %0, %1, %2;" : "=r"(r) : "f"(hi), "f"(lo));
    return r;
}

// named barrier: 4 warps of one row group (128 threads)
__device__ __forceinline__ void group_bar(int id) {
    asm volatile("bar.sync %0, %1;" :: "r"(id), "r"(128) : "memory");
}

// ============================================================================
// Problem constants
// ============================================================================
static constexpr int DIN = 256;    // K
static constexpr int BM  = 128;    // CTA M tile
static constexpr int BN  = 256;    // CTA N tile
static constexpr int BK  = 64;     // K chunk (4 k16 steps)
static constexpr int NCHUNK = DIN / BK;  // 4 (even -> tile-boundary stage reuse safe)

static constexpr int A_STRIDE = 144;   // 64 fp16 (128B) + 16B pad -> conflict-free
static constexpr int B_STRIDE = 528;   // 256 fp16 (512B) + 16B pad -> conflict-free
static constexpr int A_STAGE  = BM * A_STRIDE;   // 18432

// smem layout (dynamic, bytes)
static constexpr int SM_B    = 0;                   // 256 * 528 = 135168 (persistent)
static constexpr int SM_A    = 135168;              // 2 stages * 18432 = 36864
static constexpr int SM_BIAS = 172032;              // 256 floats = 1024
static constexpr int SMEM_SZ = 173056;

// ============================================================================
// Device scratch (no allocation allowed -> __device__ globals)
// ============================================================================
__device__ float  g_bias[512];           // [0:256) combined bias c1, [256:512) out bias c2
__device__ float  g_W1[256 * 256];
__device__ __half g_Bh[512 * 256];       // fused weight, [n][k] row-major, fp16

// ============================================================================
// Prep kernels (row-blocked): block (rg, h) computes 4 output rows x 128 cols.
// Wp / g_W1 L2 traffic divided by 4 vs the per-row version.
// ============================================================================

__device__ __forceinline__ float warp_sum(float v) {
#pragma unroll
    for (int o = 16; o > 0; o >>= 1) v += __shfl_xor_sync(0xffffffffu, v, o);
    return v;
}

// W1[o,:] = sum_i (gate[o/32]*Wc[o,i]) * Wp[i,:] ; c1[o] = dot(gate*Wc[o,:], bp)
__global__ void __launch_bounds__(128, 8)
prep_w1(const float* __restrict__ Wc, const float* __restrict__ Wp,
        const float* __restrict__ bp,
        const float* __restrict__ pre, const float* __restrict__ post,
        float* __restrict__ out_tail) {
    __shared__ float sWc[4][256];
    __shared__ float sGate;
    const int rg  = blockIdx.x >> 1;      // 0..63 (4 rows each)
    const int h   = blockIdx.x & 1;
    const int tid = threadIdx.x;
    const int col = h * 128 + tid;
    const int o0  = rg * 4;
    const int ko  = o0 >> 5;

    if (tid < 32) {
        float a = pre[ko * 256 + tid];
        float b = post[ko * 32 + tid];
        float sp = warp_sum(a * a);
        float sq = warp_sum(b * b);
        float np = fmaxf(sqrtf(sp), 1e-12f);
        float nq = fmaxf(sqrtf(sq), 1e-12f);
        float d  = warp_sum((a / np) * (b / nq));
        if (tid == 0) {
            float align = 1.0f / (1.0f + expf(-d));
            float g = (align >= 0.3f) ? align : 0.0f;
            sGate = g;
            if ((rg & 7) == 0 && h == 0) {
                out_tail[ko] = g;          // alignments
                out_tail[8 + ko] = 1.0f;   // allocation_mask
            }
        }
    }
    __syncthreads();
    const float g = sGate;
#pragma unroll
    for (int r = 0; r < 4; ++r) {
        sWc[r][tid]       = Wc[(o0 + r) * 256 + tid] * g;
        sWc[r][128 + tid] = Wc[(o0 + r) * 256 + 128 + tid] * g;
    }
    __syncthreads();

    float acc[4] = {0.f, 0.f, 0.f, 0.f};
#pragma unroll 16
    for (int i = 0; i < 256; ++i) {
        float w = Wp[i * 256 + col];
#pragma unroll
        for (int r = 0; r < 4; ++r) acc[r] += sWc[r][i] * w;
    }
#pragma unroll
    for (int r = 0; r < 4; ++r) {
        g_W1[(o0 + r) * 256 + col] = acc[r];
        g_Bh[(o0 + r) * 256 + col] = __float2half_rn(acc[r]);
    }

    // c1 for the 4 rows: warp w reduces row w (sync-free)
    if (h == 0) {
        const int w = tid >> 5, lane = tid & 31;
        float p = 0.f;
#pragma unroll
        for (int k = 0; k < 8; ++k)
            p += sWc[w][lane + 32 * k] * bp[lane + 32 * k];
        p = warp_sum(p);
        if (lane == 0) g_bias[o0 + w] = p;
    }
}

// W2[o,:] = sum_i Wo[o,i] * W1[i,:] ; c2[o] = dot(Wo[o,:], c1) + bo[o]
__global__ void __launch_bounds__(128, 8)
prep_w2(const float* __restrict__ Wo, const float* __restrict__ bo) {
    __shared__ float sWo[4][256];
    const int rg  = blockIdx.x >> 1;
    const int h   = blockIdx.x & 1;
    const int tid = threadIdx.x;
    const int col = h * 128 + tid;
    const int o0  = rg * 4;

#pragma unroll
    for (int r = 0; r < 4; ++r) {
        sWo[r][tid]       = Wo[(o0 + r) * 256 + tid];
        sWo[r][128 + tid] = Wo[(o0 + r) * 256 + 128 + tid];
    }
    __syncthreads();

    float acc[4] = {0.f, 0.f, 0.f, 0.f};
#pragma unroll 16
    for (int i = 0; i < 256; ++i) {
        float w = g_W1[i * 256 + col];
#pragma unroll
        for (int r = 0; r < 4; ++r) acc[r] += sWo[r][i] * w;
    }
#pragma unroll
    for (int r = 0; r < 4; ++r)
        g_Bh[(256 + o0 + r) * 256 + col] = __float2half_rn(acc[r]);

    if (h == 0) {
        const int w = tid >> 5, lane = tid & 31;
        float p = 0.f;
#pragma unroll
        for (int k = 0; k < 8; ++k)
            p += sWo[w][lane + 32 * k] * g_bias[lane + 32 * k];
        p = warp_sum(p);
        if (lane == 0) g_bias[256 + o0 + w] = p + bo[o0 + w];
    }
}

// ============================================================================
// Main fused GEMM (persistent CTAs, nt-split grid, cross-tile prefetch,
// per-row-group named barriers): C[131072 x 512] = x @ B^T.
// The 4 warps sharing wm form a row group: they write (STS) exactly the 32
// A-rows they read (ldmatrix), so the per-chunk handoff is bar.sync(1+wm,128)
// over 4 warps instead of a 16-warp __syncthreads. Groups self-pipeline.
// B + bias loaded once per CTA (cp.async), published by one __syncthreads.
// ============================================================================
__global__ void __launch_bounds__(512, 1)
fused_main(const float* __restrict__ x, float* __restrict__ out,
           int Brows, int ntiles) {
    extern __shared__ char smem[];
    const uint32_t sb = smem_to_u32(smem);
    const int tid  = threadIdx.x;
    const int wid  = tid >> 5, lane = tid & 31;
    const int wm   = wid & 3;               // row group (32 rows)
    const int wn   = wid >> 2;              // 4 N-warps of 64 cols

    const int split  = (int)(gridDim.x >> 1);
    const int nt     = (blockIdx.x >= split) ? 1 : 0;
    const int cid    = nt ? ((int)blockIdx.x - split) : (int)blockIdx.x;
    const int stride = nt ? ((int)gridDim.x - split) : split;

    // ---- persistent B tile (256 rows x full K) + bias, loaded once ----
    {
        const __half* Bg = g_Bh + (size_t)nt * BN * DIN;
        const uint32_t bd = sb + SM_B;
#pragma unroll
        for (int i = 0; i < 16; ++i) {
            int idx = tid + 512 * i;            // 8192 x 16B
            int row = idx >> 5, kseg = idx & 31;
            cp_async16(bd + row * B_STRIDE + kseg * 16, Bg + row * DIN + kseg * 8);
        }
        if (tid < 64)
            cp_async16(sb + SM_BIAS + tid * 16, g_bias + nt * BN + tid * 4);
        cp_commit();
    }

    // per-thread x mapping: thread writes/reads within its own row group.
    // row = wm*32 + wn*8 + lane/4 ; segs (lane&3)*4 .. +3
    const int prow  = wm * 32 + wn * 8 + (lane >> 2);
    const int pseg0 = (lane & 3) * 4;
    const size_t tile_step = (size_t)stride * BM * DIN;

    const int arow  = wm * 32 + (lane & 15);
    const uint32_t acolb = ((lane >> 4) & 1) * 16;
    const int brow0 = wn * 64 + ((lane & 7) | ((lane >> 4) << 3));
    const uint32_t bcolb = ((lane >> 3) & 1) * 16;
    const int barid = 1 + wm;

    // epilogue base: nt==0 -> combined block (second Brows*256); nt==1 -> out block
    float* hbase = out + (nt ? (size_t)0 : (size_t)Brows * 256);
    const float* bias_s = (const float*)(smem + SM_BIAS);

    // initial x prefetch (tile cid, chunk 0), then publish B once
    const float* xrow0 = x + (size_t)cid * BM * DIN + prow * DIN + pseg0 * 4;
    float4 pre[4];
    if (cid < ntiles) {
#pragma unroll
        for (int j = 0; j < 4; ++j)
            pre[j] = *(const float4*)(xrow0 + j * 4);
    }
    cp_wait0();
    __syncthreads();   // all threads' cp.async complete -> B + bias visible CTA-wide

    for (int mt = cid; mt < ntiles; mt += stride) {
        const float* xrow = x + (size_t)mt * BM * DIN + prow * DIN + pseg0 * 4;

        float acc[2][8][4];
#pragma unroll
        for (int m = 0; m < 2; m++)
#pragma unroll
            for (int n = 0; n < 8; n++)
#pragma unroll
                for (int k = 0; k < 4; k++) acc[m][n][k] = 0.f;

#pragma unroll 1
        for (int c = 0; c < NCHUNK; ++c) {
            const int s = c & 1;

            // ---- convert prefetched fp32 -> fp16 (packed cvt), STS stage s ----
            {
                char* As = smem + SM_A + s * A_STAGE;
#pragma unroll
                for (int j = 0; j < 4; ++j) {
                    uint2 hp;
                    hp.x = cvt2h(pre[j].x, pre[j].y);
                    hp.y = cvt2h(pre[j].z, pre[j].w);
                    *(uint2*)(As + prow * A_STRIDE + (pseg0 + j) * 8) = hp;
                }
            }
            group_bar(barid);   // only the 4 warps of this row group

            // ---- prefetch chunk c+1, or next tile's chunk 0 ----
            if (c + 1 < NCHUNK) {
#pragma unroll
                for (int j = 0; j < 4; ++j)
                    pre[j] = *(const float4*)(xrow + (c + 1) * BK + j * 4);
            } else if (mt + stride < ntiles) {
#pragma unroll
                for (int j = 0; j < 4; ++j)
                    pre[j] = *(const float4*)(xrow + tile_step + j * 4);
            }

            // ---- 4 k16 steps of MMA ----
            const uint32_t abase = sb + SM_A + s * A_STAGE;
            const uint32_t bks   = sb + SM_B + (uint32_t)(c * 128);
#pragma unroll
            for (int ks = 0; ks < 4; ++ks) {
                uint32_t af[2][4], bf[4][4];
#pragma unroll
                for (int m = 0; m < 2; ++m)
                    ldmx4(af[m], abase + (uint32_t)((arow + m * 16) * A_STRIDE) + acolb + ks * 32);
#pragma unroll
                for (int p = 0; p < 4; ++p)
                    ldmx4(bf[p], bks + (uint32_t)((brow0 + p * 16) * B_STRIDE) + bcolb + ks * 32);
#pragma unroll
                for (int m = 0; m < 2; ++m)
#pragma unroll
                    for (int n = 0; n < 8; ++n)
                        mma16816(acc[m][n], af[m], &bf[n >> 1][(n & 1) * 2]);
            }
        }

        // ---- epilogue: add fused bias (smem), write this CTA's output half ----
#pragma unroll
        for (int m = 0; m < 2; ++m) {
            const int row = mt * BM + wm * 32 + m * 16 + (lane >> 2);
            float* rp = hbase + (size_t)row * 256;
#pragma unroll
            for (int n = 0; n < 8; ++n) {
                const int ln = wn * 64 + n * 8 + (lane & 3) * 2;   // 0..255 column
                const float b0 = bias_s[ln], b1 = bias_s[ln + 1];
                *(float2*)(rp + ln)           = make_float2(acc[m][n][0] + b0, acc[m][n][1] + b1);
                *(float2*)(rp + ln + 8 * 256) = make_float2(acc[m][n][2] + b0, acc[m][n][3] + b1);
            }
        }
    }
}

// ============================================================================
// kernel_launch
// ============================================================================
extern "C" void kernel_launch(void* const* d_in, const int* in_sizes, int n_in,
                              void* d_out, int out_size) {
    const float* x    = (const float*)d_in[0];
    const float* Wp   = (const float*)d_in[1];
    const float* bp   = (const float*)d_in[2];
    const float* pre  = (const float*)d_in[3];
    const float* post = (const float*)d_in[4];
    const float* Wc   = (const float*)d_in[5];
    const float* Wo   = (const float*)d_in[6];
    const float* bo   = (const float*)d_in[7];
    float* out = (float*)d_out;
    const int Brows  = in_sizes[0] / 256;     // 131072
    const int ntiles = Brows / BM;            // 1024

    cudaFuncSetAttribute(fused_main, cudaFuncAttributeMaxDynamicSharedMemorySize, SMEM_SZ);

    int dev = 0, sms = 148;
    cudaGetDevice(&dev);
    cudaDeviceGetAttribute(&sms, cudaDevAttrMultiProcessorCount, dev);
    int grid = sms & ~1;                      // even split across the two N-halves
    if (grid > 2 * ntiles) grid = 2 * ntiles;

    prep_w1<<<128, 128>>>(Wc, Wp, bp, pre, post, out + (size_t)2 * Brows * 256);
    prep_w2<<<128, 128>>>(Wo, bo);
    fused_main<<<grid, 512, SMEM_SZ>>>(x, out, Brows, ntiles);
}

// round 14
// speedup vs baseline: 1.2890x; 1.0038x over previous
#include <cuda_runtime.h>
#include <cuda_fp16.h>
#include <cstdint>

// ============================================================================
// Portable PTX helpers (mma.sync / ldmatrix / cp.async only — no 'a'-gated ops)
// ============================================================================

__device__ __forceinline__ uint32_t smem_to_u32(const void* smem_ptr) {
    uint32_t addr;
    asm("{ .reg .u64 tmp; cvta.to.shared.u64 tmp, %1; cvt.u32.u64 %0, tmp; }"
        : "=r"(addr) : "l"(smem_ptr));
    return addr;
}

__device__ __forceinline__ void cp_async16(uint32_t dst, const void* src) {
    asm volatile("cp.async.cg.shared.global [%0], [%1], 16;"
                 :: "r"(dst), "l"(__cvta_generic_to_global(src)));
}
__device__ __forceinline__ void cp_commit() {
    asm volatile("cp.async.commit_group;" ::: "memory");
}
__device__ __forceinline__ void cp_wait0() {
    asm volatile("cp.async.wait_group 0;" ::: "memory");
}

__device__ __forceinline__ void ldmx4(uint32_t* r, uint32_t addr) {
    asm volatile("ldmatrix.sync.aligned.m8n8.x4.shared.b16 {%0,%1,%2,%3}, [%4];"
                 : "=r"(r[0]), "=r"(r[1]), "=r"(r[2]), "=r"(r[3]) : "r"(addr));
}

__device__ __forceinline__ void mma16816(float* c, const uint32_t* a, const uint32_t* b) {
    asm volatile(
        "mma.sync.aligned.m16n8k16.row.col.f32.f16.f16.f32 "
        "{%0,%1,%2,%3}, {%4,%5,%6,%7}, {%8,%9}, {%0,%1,%2,%3};"
        : "+f"(c[0]), "+f"(c[1]), "+f"(c[2]), "+f"(c[3])
        : "r"(a[0]), "r"(a[1]), "r"(a[2]), "r"(a[3]), "r"(b[0]), "r"(b[1]));
}

// packed fp32x2 -> fp16x2 convert (round-to-nearest, identical to __float2half_rn)
__device__ __forceinline__ uint32_t cvt2h(float lo, float hi) {
    uint32_t r;
    asm("cvt.rn.f16x2.f32 %0, %1, %2;" : "=r"(r) : "f"(hi), "f"(lo));
    return r;
}

// evict-first vector store (output is write-once, keep it out of L2)
__device__ __forceinline__ void stg_cs2(float* p, float a, float b) {
    asm volatile("st.global.cs.v2.f32 [%0], {%1, %2};"
                 :: "l"(__cvta_generic_to_global(p)), "f"(a), "f"(b) : "memory");
}

// named barrier: 4 warps of one row group (128 threads)
__device__ __forceinline__ void group_bar(int id) {
    asm volatile("bar.sync %0, %1;" :: "r"(id), "r"(128) : "memory");
}

// ============================================================================
// Problem constants
// ============================================================================
static constexpr int DIN = 256;    // K
static constexpr int BM  = 128;    // CTA M tile
static constexpr int BN  = 256;    // CTA N tile
static constexpr int BK  = 64;     // K chunk (4 k16 steps)
static constexpr int NCHUNK = DIN / BK;  // 4 (even -> tile-boundary stage reuse safe)

static constexpr int A_STRIDE = 144;   // 64 fp16 (128B) + 16B pad -> conflict-free
static constexpr int B_STRIDE = 528;   // 256 fp16 (512B) + 16B pad -> conflict-free
static constexpr int A_STAGE  = BM * A_STRIDE;   // 18432

// smem layout (dynamic, bytes)
static constexpr int SM_B    = 0;                   // 256 * 528 = 135168 (persistent)
static constexpr int SM_A    = 135168;              // 2 stages * 18432 = 36864
static constexpr int SM_BIAS = 172032;              // 256 floats = 1024
static constexpr int SMEM_SZ = 173056;

// ============================================================================
// Device scratch (no allocation allowed -> __device__ globals)
// ============================================================================
__device__ float  g_bias[512];           // [0:256) combined bias c1, [256:512) out bias c2
__device__ __half g_Bh[512 * 256];       // fused weight, [n][k] row-major, fp16

// ============================================================================
// Single prep kernel, 256 blocks x 128 threads, NO inter-block dependency:
//   blocks [0,128):  W1[o,:]  = (gate⊙Wc[o,:]) @ Wp ; c1[o] = (gate⊙Wc[o,:])·bp
//   blocks [128,256): U[o,:]  = (Wo[o,:]⊙gate-per-col) @ Wc   (own 4 rows, smem)
//                     W2[o,:] = U[o,:] @ Wp ; c2[o] = U[o,:]·bp + bo[o]
// (W2 = Wo@W1 = (Wo@gWc)@Wp by associativity.)
// ============================================================================

__device__ __forceinline__ float warp_sum(float v) {
#pragma unroll
    for (int o = 16; o > 0; o >>= 1) v += __shfl_xor_sync(0xffffffffu, v, o);
    return v;
}

__device__ __forceinline__ float gate_of(const float* pre, const float* post,
                                         int k, int lane) {
    float a = pre[k * 256 + lane];
    float b = post[k * 32 + lane];
    float sp = warp_sum(a * a);
    float sq = warp_sum(b * b);
    float np = fmaxf(sqrtf(sp), 1e-12f);
    float nq = fmaxf(sqrtf(sq), 1e-12f);
    float d  = warp_sum((a / np) * (b / nq));
    float align = 1.0f / (1.0f + expf(-d));
    return (align >= 0.3f) ? align : 0.0f;
}

__global__ void __launch_bounds__(128, 8)
prep_all(const float* __restrict__ Wc, const float* __restrict__ Wp,
         const float* __restrict__ bp,
         const float* __restrict__ pre, const float* __restrict__ post,
         const float* __restrict__ Wo, const float* __restrict__ bo,
         float* __restrict__ out_tail) {
    __shared__ float sW[4][256];
    __shared__ float sU[4][256];
    __shared__ float sGate[8];
    const int bid = blockIdx.x;
    const bool isW2 = bid >= 128;
    const int rg  = (bid & 127) >> 1;
    const int h   = bid & 1;
    const int tid = threadIdx.x;
    const int col = h * 128 + tid;
    const int o0  = rg * 4;
    const int w   = tid >> 5, lane = tid & 31;

    if (!isW2) {
        // ---- gate for this block's single nanocolumn ----
        const int ko = o0 >> 5;
        if (tid < 32) {
            float g = gate_of(pre, post, ko, lane);
            if (lane == 0) {
                sGate[0] = g;
                if ((rg & 7) == 0 && h == 0) {
                    out_tail[ko] = g;          // alignments
                    out_tail[8 + ko] = 1.0f;   // allocation_mask
                }
            }
        }
        __syncthreads();
        const float g = sGate[0];
#pragma unroll
        for (int r = 0; r < 4; ++r) {
            sW[r][tid]       = Wc[(o0 + r) * 256 + tid] * g;
            sW[r][128 + tid] = Wc[(o0 + r) * 256 + 128 + tid] * g;
        }
        __syncthreads();

        float acc[4] = {0.f, 0.f, 0.f, 0.f};
#pragma unroll 16
        for (int i = 0; i < 256; ++i) {
            float wv = Wp[i * 256 + col];
#pragma unroll
            for (int r = 0; r < 4; ++r) acc[r] += sW[r][i] * wv;
        }
#pragma unroll
        for (int r = 0; r < 4; ++r)
            g_Bh[(o0 + r) * 256 + col] = __float2half_rn(acc[r]);

        if (h == 0) {
            float p = 0.f;
#pragma unroll
            for (int k = 0; k < 8; ++k)
                p += sW[w][lane + 32 * k] * bp[lane + 32 * k];
            p = warp_sum(p);
            if (lane == 0) g_bias[o0 + w] = p;
        }
    } else {
        // ---- all 8 gates (warp w does gates w and w+4) ----
#pragma unroll
        for (int kk = w; kk < 8; kk += 4) {
            float g = gate_of(pre, post, kk, lane);
            if (lane == 0) sGate[kk] = g;
        }
        __syncthreads();

        // gated Wo rows: sW[r][j] = Wo[o0+r, j] * gate[j>>5]
#pragma unroll
        for (int r = 0; r < 4; ++r) {
            sW[r][tid]       = Wo[(o0 + r) * 256 + tid] * sGate[tid >> 5];
            sW[r][128 + tid] = Wo[(o0 + r) * 256 + 128 + tid] * sGate[(128 + tid) >> 5];
        }
        __syncthreads();

        // phase A: U[r, tid] and U[r, tid+128] (full U rows needed in phase B)
        float ua[4], ub[4];
#pragma unroll
        for (int r = 0; r < 4; ++r) { ua[r] = 0.f; ub[r] = 0.f; }
#pragma unroll 8
        for (int j = 0; j < 256; ++j) {
            float c0 = Wc[j * 256 + tid];
            float c1 = Wc[j * 256 + 128 + tid];
#pragma unroll
            for (int r = 0; r < 4; ++r) { ua[r] += sW[r][j] * c0; ub[r] += sW[r][j] * c1; }
        }
#pragma unroll
        for (int r = 0; r < 4; ++r) { sU[r][tid] = ua[r]; sU[r][128 + tid] = ub[r]; }
        __syncthreads();

        // phase B: W2[o0+r, col] = U[r,:] @ Wp[:, col]
        float acc[4] = {0.f, 0.f, 0.f, 0.f};
#pragma unroll 16
        for (int i = 0; i < 256; ++i) {
            float wv = Wp[i * 256 + col];
#pragma unroll
            for (int r = 0; r < 4; ++r) acc[r] += sU[r][i] * wv;
        }
#pragma unroll
        for (int r = 0; r < 4; ++r)
            g_Bh[(256 + o0 + r) * 256 + col] = __float2half_rn(acc[r]);

        if (h == 0) {
            float p = 0.f;
#pragma unroll
            for (int k = 0; k < 8; ++k)
                p += sU[w][lane + 32 * k] * bp[lane + 32 * k];
            p = warp_sum(p);
            if (lane == 0) g_bias[256 + o0 + w] = p + bo[o0 + w];
        }
    }
}

// ============================================================================
// Main fused GEMM (persistent CTAs, nt-split grid, cross-tile prefetch,
// per-row-group named barriers, evict-first stores): C[131072 x 512] = x @ B^T.
// ============================================================================
__global__ void __launch_bounds__(512, 1)
fused_main(const float* __restrict__ x, float* __restrict__ out,
           int Brows, int ntiles) {
    extern __shared__ char smem[];
    const uint32_t sb = smem_to_u32(smem);
    const int tid  = threadIdx.x;
    const int wid  = tid >> 5, lane = tid & 31;
    const int wm   = wid & 3;               // row group (32 rows)
    const int wn   = wid >> 2;              // 4 N-warps of 64 cols

    const int split  = (int)(gridDim.x >> 1);
    const int nt     = (blockIdx.x >= split) ? 1 : 0;
    const int cid    = nt ? ((int)blockIdx.x - split) : (int)blockIdx.x;
    const int stride = nt ? ((int)gridDim.x - split) : split;

    // ---- persistent B tile (256 rows x full K) + bias, loaded once ----
    {
        const __half* Bg = g_Bh + (size_t)nt * BN * DIN;
        const uint32_t bd = sb + SM_B;
#pragma unroll
        for (int i = 0; i < 16; ++i) {
            int idx = tid + 512 * i;            // 8192 x 16B
            int row = idx >> 5, kseg = idx & 31;
            cp_async16(bd + row * B_STRIDE + kseg * 16, Bg + row * DIN + kseg * 8);
        }
        if (tid < 64)
            cp_async16(sb + SM_BIAS + tid * 16, g_bias + nt * BN + tid * 4);
        cp_commit();
    }

    // per-thread x mapping: thread writes/reads within its own row group.
    const int prow  = wm * 32 + wn * 8 + (lane >> 2);
    const int pseg0 = (lane & 3) * 4;
    const size_t tile_step = (size_t)stride * BM * DIN;

    const int arow  = wm * 32 + (lane & 15);
    const uint32_t acolb = ((lane >> 4) & 1) * 16;
    const int brow0 = wn * 64 + ((lane & 7) | ((lane >> 4) << 3));
    const uint32_t bcolb = ((lane >> 3) & 1) * 16;
    const int barid = 1 + wm;

    // epilogue base: nt==0 -> combined block (second Brows*256); nt==1 -> out block
    float* hbase = out + (nt ? (size_t)0 : (size_t)Brows * 256);
    const float* bias_s = (const float*)(smem + SM_BIAS);

    // initial x prefetch (tile cid, chunk 0), then publish B once
    const float* xrow0 = x + (size_t)cid * BM * DIN + prow * DIN + pseg0 * 4;
    float4 pre[4];
    if (cid < ntiles) {
#pragma unroll
        for (int j = 0; j < 4; ++j)
            pre[j] = *(const float4*)(xrow0 + j * 4);
    }
    cp_wait0();
    __syncthreads();   // all threads' cp.async complete -> B + bias visible CTA-wide

    for (int mt = cid; mt < ntiles; mt += stride) {
        const float* xrow = x + (size_t)mt * BM * DIN + prow * DIN + pseg0 * 4;

        float acc[2][8][4];
#pragma unroll
        for (int m = 0; m < 2; m++)
#pragma unroll
            for (int n = 0; n < 8; n++)
#pragma unroll
                for (int k = 0; k < 4; k++) acc[m][n][k] = 0.f;

#pragma unroll 1
        for (int c = 0; c < NCHUNK; ++c) {
            const int s = c & 1;

            // ---- convert prefetched fp32 -> fp16 (packed cvt), STS stage s ----
            {
                char* As = smem + SM_A + s * A_STAGE;
#pragma unroll
                for (int j = 0; j < 4; ++j) {
                    uint2 hp;
                    hp.x = cvt2h(pre[j].x, pre[j].y);
                    hp.y = cvt2h(pre[j].z, pre[j].w);
                    *(uint2*)(As + prow * A_STRIDE + (pseg0 + j) * 8) = hp;
                }
            }
            group_bar(barid);   // only the 4 warps of this row group

            // ---- prefetch chunk c+1, or next tile's chunk 0 ----
            if (c + 1 < NCHUNK) {
#pragma unroll
                for (int j = 0; j < 4; ++j)
                    pre[j] = *(const float4*)(xrow + (c + 1) * BK + j * 4);
            } else if (mt + stride < ntiles) {
#pragma unroll
                for (int j = 0; j < 4; ++j)
                    pre[j] = *(const float4*)(xrow + tile_step + j * 4);
            }

            // ---- 4 k16 steps of MMA ----
            const uint32_t abase = sb + SM_A + s * A_STAGE;
            const uint32_t bks   = sb + SM_B + (uint32_t)(c * 128);
#pragma unroll
            for (int ks = 0; ks < 4; ++ks) {
                uint32_t af[2][4], bf[4][4];
#pragma unroll
                for (int m = 0; m < 2; ++m)
                    ldmx4(af[m], abase + (uint32_t)((arow + m * 16) * A_STRIDE) + acolb + ks * 32);
#pragma unroll
                for (int p = 0; p < 4; ++p)
                    ldmx4(bf[p], bks + (uint32_t)((brow0 + p * 16) * B_STRIDE) + bcolb + ks * 32);
#pragma unroll
                for (int m = 0; m < 2; ++m)
#pragma unroll
                    for (int n = 0; n < 8; ++n)
                        mma16816(acc[m][n], af[m], &bf[n >> 1][(n & 1) * 2]);
            }
        }

        // ---- epilogue: add fused bias (smem), evict-first stores ----
#pragma unroll
        for (int m = 0; m < 2; ++m) {
            const int row = mt * BM + wm * 32 + m * 16 + (lane >> 2);
            float* rp = hbase + (size_t)row * 256;
#pragma unroll
            for (int n = 0; n < 8; ++n) {
                const int ln = wn * 64 + n * 8 + (lane & 3) * 2;   // 0..255 column
                const float b0 = bias_s[ln], b1 = bias_s[ln + 1];
                stg_cs2(rp + ln,           acc[m][n][0] + b0, acc[m][n][1] + b1);
                stg_cs2(rp + ln + 8 * 256, acc[m][n][2] + b0, acc[m][n][3] + b1);
            }
        }
    }
}

// ============================================================================
// kernel_launch
// ============================================================================
extern "C" void kernel_launch(void* const* d_in, const int* in_sizes, int n_in,
                              void* d_out, int out_size) {
    const float* x    = (const float*)d_in[0];
    const float* Wp   = (const float*)d_in[1];
    const float* bp   = (const float*)d_in[2];
    const float* pre  = (const float*)d_in[3];
    const float* post = (const float*)d_in[4];
    const float* Wc   = (const float*)d_in[5];
    const float* Wo   = (const float*)d_in[6];
    const float* bo   = (const float*)d_in[7];
    float* out = (float*)d_out;
    const int Brows  = in_sizes[0] / 256;     // 131072
    const int ntiles = Brows / BM;            // 1024

    cudaFuncSetAttribute(fused_main, cudaFuncAttributeMaxDynamicSharedMemorySize, SMEM_SZ);

    int dev = 0, sms = 148;
    cudaGetDevice(&dev);
    cudaDeviceGetAttribute(&sms, cudaDevAttrMultiProcessorCount, dev);
    int grid = sms & ~1;                      // even split across the two N-halves
    if (grid > 2 * ntiles) grid = 2 * ntiles;

    prep_all<<<256, 128>>>(Wc, Wp, bp, pre, post, Wo, bo,
                           out + (size_t)2 * Brows * 256);
    fused_main<<<grid, 512, SMEM_SZ>>>(x, out, Brows, ntiles);
}